// round 2
// baseline (speedup 1.0000x reference)
#include <cuda_runtime.h>
#include <cuda_bf16.h>
#include <cstdint>

// MaddnessConv2d, round 2: 4 threads/pixel channel split.
//   x:            (16, 64, 56, 56) f32
//   split_idxs:   (16, 4) i32
//   split_vals:   (16, 4, 8) f32
//   lookup_tables:(16, 16, 64) f32
//   bias:         (64,) f32
//   out:          (16, 64, 56, 56) f32
//
// Per pixel: 16 codebook codes (4-bit each, from 4 threshold steps on 4 fixed
// gathered x scalars per codebook), then out[ch] = sum_cb LUT[cb][e_cb][ch]+bias.
// 4 lanes share one pixel: lane `part` encodes codebooks [4part,4part+4),
// codes exchanged via 2 butterfly shuffles (16 nibbles in a u64), then each
// lane accumulates its 16 channels [16part,16part+16) for all 16 codebooks.

#define NCB   16
#define KENC  16
#define HW    3136          // 56*56
#define WID   56
#define NPIX  50176         // 16*56*56
#define TPB   512
#define NBLK  392           // 392*512 == 4*50176 exactly

// dynamic smem layout:
//   float4 s_lut[16*16*16]       65536 B  (transpose-XOR swizzled)
//   float  s_bias[64]              256 B
//   float  s_sval[16*4*8]         2048 B
//   int    s_off[64]               256 B
//   int    s_dy[64]                256 B
//   int    s_dx[64]                256 B
#define SMEM_BYTES (65536 + 256 + 2048 + 256 + 256 + 256)

#define ADD_F32X2(out, a, b) \
    asm("add.rn.f32x2 %0, %1, %2;" : "=l"(out) : "l"(a), "l"(b))
#define PACK_F32X2(out, lo, hi) \
    asm("mov.b64 %0, {%1, %2};" : "=l"(out) : "f"(lo), "f"(hi))
#define UNPACK_F32X2(lo, hi, in) \
    asm("mov.b64 {%0, %1}, %2;" : "=f"(lo), "=f"(hi) : "l"(in))

__global__ __launch_bounds__(TPB, 2) void maddness_conv2d_kernel(
    const float* __restrict__ x,
    const int*   __restrict__ split_idxs,
    const float* __restrict__ split_vals,
    const float* __restrict__ lut,
    const float* __restrict__ bias,
    float*       __restrict__ out)
{
    extern __shared__ char smem_raw[];
    float4* s_lut  = (float4*)smem_raw;
    float*  s_bias = (float*)(smem_raw + 65536);
    float*  s_sval = (float*)(smem_raw + 65536 + 256);
    int*    s_off  = (int*)  (smem_raw + 65536 + 256 + 2048);
    int*    s_dy   = (int*)  (smem_raw + 65536 + 256 + 2048 + 256);
    int*    s_dx   = (int*)  (smem_raw + 65536 + 256 + 2048 + 512);

    const int tid = threadIdx.x;

    // --- cooperative smem fill ---
    // LUT row (cb,e): logical float4 slot j (channels 4j..4j+3) stored at
    // physical slot ((j&3)<<2 | (j>>2)) ^ e  (transpose-then-XOR swizzle).
    const float4* lut4 = (const float4*)lut;
    #pragma unroll
    for (int i = tid; i < NCB * KENC * 16; i += TPB) {
        int j = i & 15;
        int e = (i >> 4) & 15;
        int ps = (((j & 3) << 2) | (j >> 2)) ^ e;
        s_lut[(i & ~15) | ps] = lut4[i];
    }
    if (tid < 64) {
        int cb = tid >> 2;                     // tid = cb*4 + t
        int si = split_idxs[tid];
        int f  = cb * 36 + si;
        int ch = f / 9;
        int r  = f - ch * 9;
        int dy = r / 3 - 1;
        int dx = r - (r / 3) * 3 - 1;
        s_off[tid] = ch * HW + dy * WID + dx;
        s_dy[tid]  = dy;
        s_dx[tid]  = dx;
        s_bias[tid] = bias[tid];
    }
    if (tid < NCB * 32) s_sval[tid] = split_vals[tid];
    __syncthreads();

    // --- per-pixel work, 4 lanes per pixel ---
    const int gt   = blockIdx.x * TPB + tid;
    const int p    = gt >> 2;                  // pixel index, < NPIX always
    const int part = gt & 3;                   // channel quarter / codebook quarter
    const int b    = p / HW;
    const int rem  = p - b * HW;
    const int y    = rem / WID;
    const int xw   = rem - y * WID;
    const float* xb = x + (size_t)b * 64 * HW + rem;

    // Encode my 4 codebooks: cb = 4*part + c
    unsigned int my = 0;
    #pragma unroll
    for (int c = 0; c < 4; c++) {
        const int cb = part * 4 + c;
        int e = 0;
        #pragma unroll
        for (int t = 0; t < 4; t++) {
            const int idx = cb * 4 + t;
            const int dy = s_dy[idx];
            const int dx = s_dx[idx];
            float v = 0.0f;
            if ((unsigned)(y + dy) < 56u && (unsigned)(xw + dx) < 56u)
                v = __ldg(xb + s_off[idx]);
            const float thr = s_sval[cb * 32 + t * 8 + e];
            e = 2 * e + (v >= thr ? 1 : 0);
        }
        my |= (unsigned)e << (4 * c);
    }

    // Exchange: lanes (l^1, l^2) are the other parts of the same pixel.
    unsigned long long u = (unsigned long long)my << (16 * part);
    u |= __shfl_xor_sync(0xffffffffu, u, 1);
    u |= __shfl_xor_sync(0xffffffffu, u, 2);

    // Accumulate my 16 channels [16*part, 16*part+16) over all 16 codebooks.
    unsigned long long acc[8];
    const unsigned long long* biasp =
        (const unsigned long long*)(s_bias + 16 * part);
    #pragma unroll
    for (int h = 0; h < 8; h++) acc[h] = biasp[h];

    #pragma unroll
    for (int cb = 0; cb < NCB; cb++) {
        const unsigned e = (unsigned)(u >> (4 * cb)) & 15u;
        const float4* row = s_lut + (cb * 16 + (int)e) * 16;
        #pragma unroll
        for (int q = 0; q < 4; q++) {
            // logical slot j = 4*part + q -> physical ((q<<2)|part)^e
            float4 v = row[((q << 2) | part) ^ (int)e];
            unsigned long long lo, hi;
            PACK_F32X2(lo, v.x, v.y);
            PACK_F32X2(hi, v.z, v.w);
            ADD_F32X2(acc[2 * q],     acc[2 * q],     lo);
            ADD_F32X2(acc[2 * q + 1], acc[2 * q + 1], hi);
        }
    }

    // --- write: out[b][ch][y][x], ch = 16*part + 4*q + k ---
    float* ob = out + (size_t)b * 64 * HW + rem + (size_t)(16 * part) * HW;
    #pragma unroll
    for (int q = 0; q < 4; q++) {
        float f0, f1, f2, f3;
        UNPACK_F32X2(f0, f1, acc[2 * q]);
        UNPACK_F32X2(f2, f3, acc[2 * q + 1]);
        ob[(4 * q + 0) * HW] = f0;
        ob[(4 * q + 1) * HW] = f1;
        ob[(4 * q + 2) * HW] = f2;
        ob[(4 * q + 3) * HW] = f3;
    }
}

extern "C" void kernel_launch(void* const* d_in, const int* in_sizes, int n_in,
                              void* d_out, int out_size)
{
    const float* x    = (const float*)d_in[0];
    const int*   sidx = (const int*)  d_in[1];
    const float* sval = (const float*)d_in[2];
    const float* lut  = (const float*)d_in[3];
    const float* bias = (const float*)d_in[4];
    float* out = (float*)d_out;

    cudaFuncSetAttribute(maddness_conv2d_kernel,
                         cudaFuncAttributeMaxDynamicSharedMemorySize,
                         SMEM_BYTES);

    maddness_conv2d_kernel<<<NBLK, TPB, SMEM_BYTES>>>(x, sidx, sval, lut, bias, out);
}

// round 3
// speedup vs baseline: 1.4820x; 1.4820x over previous
#include <cuda_runtime.h>
#include <cuda_bf16.h>
#include <cstdint>

// MaddnessConv2d, round 3: conflict-free LDS via lane-rotation + smem un-rotate.
//   x:            (16, 64, 56, 56) f32
//   split_idxs:   (16, 4) i32
//   split_vals:   (16, 4, 8) f32
//   lookup_tables:(16, 16, 64) f32
//   bias:         (64,) f32
//   out:          (16, 64, 56, 56) f32
//
// Per pixel: 16 4-bit codes (4 threshold steps on 4 fixed gathered x scalars
// per codebook), then out[ch] = sum_cb LUT[cb][e_cb][ch] + bias[ch].
//
// LDS conflict elimination: LUT rows are 256B (bank-neutral base). Lane l
// reads slot (r + l) & 15 at step r -> bank-group (r+l)&7, distinct within
// every 8-lane LDS phase, independent of the data-dependent code e.
// Register r therefore holds channel-group (r + l) & 15; un-rotated at the
// end via a 32KB smem transpose that reuses the (dead) LUT region.

#define NCB   16
#define KENC  16
#define HW    3136          // 56*56
#define WID   56
#define NPIX  50176         // 16*56*56
#define TPB   128
#define NBLK  392           // 392*128 == 50176 exactly

// dynamic smem layout:
//   float4 s_lut[16*16*16]   65536 B  (identity layout; reused as transpose buf)
//   float  s_bias[64]          256 B
//   float  s_sval[16*4*8]     2048 B
//   int    s_off[64]           256 B
//   int    s_kpos[64]          256 B
#define SMEM_BYTES (65536 + 256 + 2048 + 256 + 256)

#define ADD_F32X2(out, a, b) \
    asm("add.rn.f32x2 %0, %1, %2;" : "=l"(out) : "l"(a), "l"(b))
#define PACK_F32X2(out, lo, hi) \
    asm("mov.b64 %0, {%1, %2};" : "=l"(out) : "f"(lo), "f"(hi))
#define UNPACK_F32X2(lo, hi, in) \
    asm("mov.b64 {%0, %1}, %2;" : "=f"(lo), "=f"(hi) : "l"(in))

__global__ __launch_bounds__(TPB, 3) void maddness_conv2d_kernel(
    const float* __restrict__ x,
    const int*   __restrict__ split_idxs,
    const float* __restrict__ split_vals,
    const float* __restrict__ lut,
    const float* __restrict__ bias,
    float*       __restrict__ out)
{
    extern __shared__ char smem_raw[];
    float4* s_lut  = (float4*)smem_raw;
    float*  s_bias = (float*)(smem_raw + 65536);
    float*  s_sval = (float*)(smem_raw + 65536 + 256);
    int*    s_off  = (int*)  (smem_raw + 65536 + 256 + 2048);
    int*    s_kpos = (int*)  (smem_raw + 65536 + 256 + 2048 + 256);

    const int tid = threadIdx.x;

    // --- cooperative smem fill (LUT identity layout) ---
    const float4* lut4 = (const float4*)lut;
    #pragma unroll
    for (int i = tid; i < NCB * KENC * 16; i += TPB) s_lut[i] = lut4[i];
    if (tid < 64) {
        int cb = tid >> 2;                     // tid = cb*4 + t
        int si = split_idxs[tid];
        int f  = cb * 36 + si;
        int ch = f / 9;
        int r  = f - ch * 9;                   // kernel position 0..8
        int dy = r / 3 - 1;
        int dx = r - (r / 3) * 3 - 1;
        s_off[tid]  = ch * HW + dy * WID + dx;
        s_kpos[tid] = r;
        s_bias[tid] = bias[tid];
    }
    #pragma unroll
    for (int i = tid; i < NCB * 32; i += TPB) s_sval[i] = split_vals[i];
    __syncthreads();

    // --- per-pixel indices ---
    const int p   = blockIdx.x * TPB + tid;    // exact grid: p < NPIX always
    const int b   = p / HW;
    const int rem = p - b * HW;
    const int y   = rem / WID;
    const int xw  = rem - y * WID;
    const float* xb = x + (size_t)b * 64 * HW + rem;

    // 3x3 validity bitmask (pad=1)
    unsigned vm = 0;
    #pragma unroll
    for (int ki = 0; ki < 3; ki++)
        #pragma unroll
        for (int kj = 0; kj < 3; kj++) {
            bool ok = ((unsigned)(y + ki - 1) < 56u) & ((unsigned)(xw + kj - 1) < 56u);
            vm |= (ok ? 1u : 0u) << (ki * 3 + kj);
        }

    // --- encode all 16 codebooks into a u64 of nibbles ---
    unsigned long long codes = 0ull;
    #pragma unroll
    for (int cb = 0; cb < NCB; cb++) {
        int e = 0;
        #pragma unroll
        for (int t = 0; t < 4; t++) {
            const int idx = cb * 4 + t;
            float v = 0.0f;
            if ((vm >> s_kpos[idx]) & 1u) v = __ldg(xb + s_off[idx]);
            const float thr = s_sval[cb * 32 + t * 8 + e];
            e = 2 * e + (v >= thr ? 1 : 0);
        }
        codes |= (unsigned long long)e << (4 * cb);
    }

    // --- accumulate: register r holds channel-group g = (r + rot) & 15 ---
    const int rot = tid & 15;
    unsigned long long accA[16], accB[16];     // (ch0,ch1) and (ch2,ch3) of group
    const float4* bias4 = (const float4*)s_bias;
    #pragma unroll
    for (int r = 0; r < 16; r++) {
        float4 bv = bias4[(r + rot) & 15];
        PACK_F32X2(accA[r], bv.x, bv.y);
        PACK_F32X2(accB[r], bv.z, bv.w);
    }

    #pragma unroll
    for (int cb = 0; cb < NCB; cb++) {
        const int e = (int)((codes >> (4 * cb)) & 15ull);
        const float4* row = s_lut + (cb * 16 + e) * 16;
        #pragma unroll
        for (int r = 0; r < 16; r++) {
            float4 v = row[(r + rot) & 15];
            unsigned long long lo, hi;
            PACK_F32X2(lo, v.x, v.y);
            PACK_F32X2(hi, v.z, v.w);
            ADD_F32X2(accA[r], accA[r], lo);
            ADD_F32X2(accB[r], accB[r], hi);
        }
    }

    // --- un-rotate via smem transpose (reuse LUT region; LUT is dead now) ---
    __syncthreads();
    float4* s_buf = (float4*)smem_raw;         // [16 groups][TPB threads]
    #pragma unroll
    for (int r = 0; r < 16; r++) {
        float f0, f1, f2, f3;
        UNPACK_F32X2(f0, f1, accA[r]);
        UNPACK_F32X2(f2, f3, accB[r]);
        s_buf[(((r + rot) & 15) * TPB) + tid] = make_float4(f0, f1, f2, f3);
    }
    __syncthreads();

    // --- coalesced store: out[b][ch][y][x], ch = 4g + k ---
    float* ob = out + (size_t)b * 64 * HW + rem;
    #pragma unroll
    for (int g = 0; g < 16; g++) {
        float4 v = s_buf[g * TPB + tid];
        ob[(4 * g + 0) * HW] = v.x;
        ob[(4 * g + 1) * HW] = v.y;
        ob[(4 * g + 2) * HW] = v.z;
        ob[(4 * g + 3) * HW] = v.w;
    }
}

extern "C" void kernel_launch(void* const* d_in, const int* in_sizes, int n_in,
                              void* d_out, int out_size)
{
    const float* x    = (const float*)d_in[0];
    const int*   sidx = (const int*)  d_in[1];
    const float* sval = (const float*)d_in[2];
    const float* lut  = (const float*)d_in[3];
    const float* bias = (const float*)d_in[4];
    float* out = (float*)d_out;

    cudaFuncSetAttribute(maddness_conv2d_kernel,
                         cudaFuncAttributeMaxDynamicSharedMemorySize,
                         SMEM_BYTES);

    maddness_conv2d_kernel<<<NBLK, TPB, SMEM_BYTES>>>(x, sidx, sval, lut, bias, out);
}